// round 4
// baseline (speedup 1.0000x reference)
#include <cuda_runtime.h>

#define SEQ 512
#define BATCH 256
#define EMB 300
#define HID 10
#define G3 30
#define K4C (EMB / 4)      // 75
#define CHUNK 64
#define NCH (SEQ / CHUNK)  // 8

// dynamic SMEM layout:
//   sw   : EMB*16 ull  (f32x2 weight pairs, 16 slots/k, 15 used)   38400 B
//   gbuf : float[2][CHUNK][32] gi double buffer                    16384 B
#define SW_ULL (EMB * 16)
#define SMEM_BYTES (SW_ULL * 8 + 2 * CHUNK * 32 * 4)

// ---------- helpers ----------
__device__ __forceinline__ unsigned long long pk2(float lo, float hi) {
    unsigned long long r;
    asm("mov.b64 %0, {%1, %2};" : "=l"(r) : "f"(lo), "f"(hi));
    return r;
}
__device__ __forceinline__ void upk2(unsigned long long v, float& lo, float& hi) {
    asm("mov.b64 {%0, %1}, %2;" : "=f"(lo), "=f"(hi) : "l"(v));
}
__device__ __forceinline__ unsigned long long fma2(unsigned long long a,
                                                   unsigned long long b,
                                                   unsigned long long c) {
    unsigned long long d;
    asm("fma.rn.f32x2 %0, %1, %2, %3;" : "=l"(d) : "l"(a), "l"(b), "l"(c));
    return d;
}
__device__ __forceinline__ float tanha(float x) {
    float y;
    asm("tanh.approx.f32 %0, %1;" : "=f"(y) : "f"(x));
    return y;
}
__device__ __forceinline__ float sig_full(float x) {
    return fmaf(tanha(0.5f * x), 0.5f, 0.5f);
}
__device__ __forceinline__ float getc(float4 v, int i) {
    return i == 0 ? v.x : i == 1 ? v.y : i == 2 ? v.z : v.w;
}

// ---------- fused producer-consumer kernel: 1 block = 1 batch element ------
// warps 0-3: gi GEMM producers (chunked, double-buffered in SMEM)
// warp 4   : GRU recurrence consumer + backward-dir step + linear head
__global__ void __launch_bounds__(160) k_fused(
    const float* __restrict__ x,
    const float* __restrict__ w_ihf, const float* __restrict__ b_ihf,
    const float* __restrict__ w_ihb, const float* __restrict__ b_ihb,
    const float* __restrict__ whh,  const float* __restrict__ bhhf,
    const float* __restrict__ bhhb, const float* __restrict__ wlin,
    const float* __restrict__ blin, float* __restrict__ out)
{
    extern __shared__ unsigned long long sm[];
    unsigned long long* sw = sm;
    ulonglong2* swv = (ulonglong2*)sm;
    float* gbuf = (float*)(sm + SW_ULL);

    const int tid = threadIdx.x;
    const int b   = blockIdx.x;
    const bool is_rec = (tid >= 128);
    const unsigned m = 0xffffffffu;

    // ================= producer setup + weight staging =================
    const int q  = tid & 3;   // gate quarter (pairs 4q..4q+3)
    const int ro = tid >> 2;  // row pair index 0..31
    unsigned long long biasp[4];

    if (!is_rec) {
        // stage w_ih_f as f32x2 pairs, rows 0..19 (pairs 0..9) scaled by 0.5
        for (int i = tid; i < EMB * 16; i += 128) {
            int k = i >> 4, p = i & 15;
            unsigned long long v = 0ULL;
            if (p < 15) {
                float sc = (p < 10) ? 0.5f : 1.0f;
                v = pk2(sc * __ldg(w_ihf + (2 * p) * EMB + k),
                        sc * __ldg(w_ihf + (2 * p + 1) * EMB + k));
            }
            sw[i] = v;
        }
#pragma unroll
        for (int p = 0; p < 4; ++p) {
            int P = 4 * q + p;
            biasp[p] = 0ULL;
            if (P < 15) {
                float sc = (P < 10) ? 0.5f : 1.0f;
                biasp[p] = pk2(sc * __ldg(b_ihf + 2 * P),
                               sc * __ldg(b_ihf + 2 * P + 1));
            }
        }
    }

    // ================= rec warp setup (overlapped with staging) =========
    const int l   = tid - 128;          // lane for rec warp
    const int l30 = (l >= 0 && l < G3) ? l : 0;
    float gb = 0.0f, wv[HID], biasr = 0.0f;
    float h[HID], hown = 0.0f;

    if (is_rec) {
        // backward-direction gi at s = S-1 (one-time dot, 30 lanes)
        const float4* xq = (const float4*)(x + ((size_t)b * SEQ + SEQ - 1) * EMB);
        const float4* wq = (const float4*)(w_ihb + (size_t)l30 * EMB);
        float a0 = 0, a1 = 0, a2 = 0, a3 = 0;
#pragma unroll 5
        for (int k4 = 0; k4 < K4C; ++k4) {
            float4 xv = __ldg(xq + k4);
            float4 wv4 = __ldg(wq + k4);
            a0 = fmaf(xv.x, wv4.x, a0);
            a1 = fmaf(xv.y, wv4.y, a1);
            a2 = fmaf(xv.z, wv4.z, a2);
            a3 = fmaf(xv.w, wv4.w, a3);
        }
        gb = (a0 + a1) + (a2 + a3) + ((l < G3) ? __ldg(b_ihb + l) : 0.0f);

        const float scl = (l < 20) ? 0.5f : 1.0f;
#pragma unroll
        for (int k = 0; k < HID; ++k) wv[k] = 0.0f;
        if (l < G3) {
#pragma unroll
            for (int k = 0; k < HID; ++k) wv[k] = scl * __ldg(whh + l * HID + k);
            biasr = scl * __ldg(bhhf + l);
        }
#pragma unroll
        for (int k = 0; k < HID; ++k) h[k] = 0.0f;
    }

    __syncthreads();

    // ================= lockstep pipeline ================================
    for (int c = 0; c <= NCH; ++c) {
        // ---- producers: compute chunk c into gbuf[c&1] ----
        if (!is_rec && c < NCH) {
            float* go = gbuf + (c & 1) * (CHUNK * 32);
            const int sl0 = 2 * ro;  // local rows sl0, sl0+1
            const float4* xr0 =
                (const float4*)(x + ((size_t)b * SEQ + c * CHUNK + sl0) * EMB);

            unsigned long long acc[2][4];
#pragma unroll
            for (int p = 0; p < 4; ++p) {
                acc[0][p] = biasp[p];
                acc[1][p] = biasp[p];
            }

#pragma unroll 5
            for (int k4 = 0; k4 < K4C; ++k4) {
                float4 xv0 = __ldg(xr0 + k4);
                float4 xv1 = __ldg(xr0 + K4C + k4);   // row +1 (EMB floats)
#pragma unroll
                for (int kk = 0; kk < 4; ++kk) {
                    ulonglong2 w0 = swv[(4 * k4 + kk) * 8 + 2 * q];
                    ulonglong2 w1 = swv[(4 * k4 + kk) * 8 + 2 * q + 1];
                    {
                        float xs = getc(xv0, kk);
                        unsigned long long xx = pk2(xs, xs);
                        acc[0][0] = fma2(xx, w0.x, acc[0][0]);
                        acc[0][1] = fma2(xx, w0.y, acc[0][1]);
                        acc[0][2] = fma2(xx, w1.x, acc[0][2]);
                        acc[0][3] = fma2(xx, w1.y, acc[0][3]);
                    }
                    {
                        float xs = getc(xv1, kk);
                        unsigned long long xx = pk2(xs, xs);
                        acc[1][0] = fma2(xx, w0.x, acc[1][0]);
                        acc[1][1] = fma2(xx, w0.y, acc[1][1]);
                        acc[1][2] = fma2(xx, w1.x, acc[1][2]);
                        acc[1][3] = fma2(xx, w1.y, acc[1][3]);
                    }
                }
            }

#pragma unroll
            for (int j = 0; j < 2; ++j) {
                float* gr = go + (sl0 + j) * 32;
#pragma unroll
                for (int p = 0; p < 4; ++p) {
                    int P = 4 * q + p;
                    if (P < 15) {
                        float lo, hi;
                        upk2(acc[j][p], lo, hi);
                        *(float2*)(gr + 2 * P) = make_float2(lo, hi);
                    }
                }
            }
        }

        // ---- consumer: run chunk c-1 ----
        if (is_rec && c >= 1) {
            const float* gi_s = gbuf + ((c - 1) & 1) * (CHUNK * 32);
            float gcur = gi_s[l30];
#pragma unroll 4
            for (int u = 0; u < CHUNK; ++u) {
                int un = (u + 1 < CHUNK) ? u + 1 : u;
                float gnext = gi_s[un * 32 + l30];   // 1-step LDS prefetch

                float inn = __shfl_sync(m, gcur, l + 20);

                float a0 = biasr, a1 = 0.0f, a2 = 0.0f, a3 = 0.0f;
                a0 = fmaf(h[0], wv[0], a0);  a1 = fmaf(h[1], wv[1], a1);
                a2 = fmaf(h[2], wv[2], a2);  a3 = fmaf(h[3], wv[3], a3);
                a0 = fmaf(h[4], wv[4], a0);  a1 = fmaf(h[5], wv[5], a1);
                a2 = fmaf(h[6], wv[6], a2);  a3 = fmaf(h[7], wv[7], a3);
                a0 = fmaf(h[8], wv[8], a0);  a1 = fmaf(h[9], wv[9], a1);
                float gh = (a0 + a1) + (a2 + a3);
                float s  = gcur + gh;

                float t   = tanha(s);                 // tanh(pre/2) on r,z lanes
                float ghn = __shfl_sync(m, gh, l + 20);
                float tz  = __shfl_sync(m, t,  l + 10);

                float r  = fmaf(t,  0.5f, 0.5f);
                float z  = fmaf(tz, 0.5f, 0.5f);
                float n  = tanha(fmaf(r, ghn, inn));
                float hn = fmaf(z, hown - n, n);

#pragma unroll
                for (int k = 0; k < HID; ++k) h[k] = __shfl_sync(m, hn, k);
                hown = hn;
                gcur = gnext;
            }
        }

        __syncthreads();
    }

    // ================= epilogue: backward step + linear head ===========
    if (is_rec) {
        float bb  = (l < G3) ? __ldg(bhhb + l) : 0.0f;
        float sb  = gb + bb;
        float azb = __shfl_sync(m, sb, l + 10);
        float gbn = __shfl_sync(m, gb, l + 20);
        float bbn = __shfl_sync(m, bb, l + 20);
        float rb  = sig_full(sb);
        float zb  = sig_full(azb);
        float nb  = tanha(fmaf(rb, bbn, gbn));
        float hbv = (1.0f - zb) * nb;

        float cacc = 0.0f;
        if (l < HID) cacc = __ldg(wlin + l) * hown + __ldg(wlin + HID + l) * hbv;
        cacc += __shfl_down_sync(m, cacc, 8);
        cacc += __shfl_down_sync(m, cacc, 4);
        cacc += __shfl_down_sync(m, cacc, 2);
        cacc += __shfl_down_sync(m, cacc, 1);
        if (l == 0) out[b] = cacc + __ldg(blin);
    }
}

extern "C" void kernel_launch(void* const* d_in, const int* in_sizes, int n_in,
                              void* d_out, int out_size)
{
    const float* x      = (const float*)d_in[0];
    const float* w_ih_f = (const float*)d_in[1];
    const float* w_hh_f = (const float*)d_in[2];
    const float* b_ih_f = (const float*)d_in[3];
    const float* b_hh_f = (const float*)d_in[4];
    const float* w_ih_b = (const float*)d_in[5];
    /* w_hh_b (d_in[6]) mathematically unused: h0 = 0 for the single bwd step */
    const float* b_ih_b = (const float*)d_in[7];
    const float* b_hh_b = (const float*)d_in[8];
    const float* w_lin  = (const float*)d_in[9];
    const float* b_lin  = (const float*)d_in[10];
    float* out = (float*)d_out;

    cudaFuncSetAttribute(k_fused, cudaFuncAttributeMaxDynamicSharedMemorySize,
                         SMEM_BYTES);
    k_fused<<<BATCH, 160, SMEM_BYTES>>>(x, w_ih_f, b_ih_f, w_ih_b, b_ih_b,
                                        w_hh_f, b_hh_f, b_hh_b, w_lin, b_lin,
                                        out);
}

// round 5
// speedup vs baseline: 2.4408x; 2.4408x over previous
#include <cuda_runtime.h>
#include <cstdint>

#define SEQ 512
#define BATCH 256
#define EMB 300
#define HID 10
#define G3 30
#define K4C 75
#define CHUNK 32
#define NCH (SEQ / CHUNK)          // 16
#define XTILE_B (CHUNK * EMB * 4)  // 38400 bytes per x chunk
#define SW_ULL (EMB * 16)          // weight table: 4800 ull = 38400 B
#define XOFF_B 38400
#define GIOFF_B (XOFF_B + 4 * XTILE_B)   // 192000
#define GI_B (CHUNK * 32 * 4)            // 4096
#define MBOFF_B (GIOFF_B + 4 * GI_B)     // 208384
#define SMEM_B (MBOFF_B + 64)            // 208448

// ---------- scalar helpers ----------
__device__ __forceinline__ unsigned long long pk2(float lo, float hi) {
    unsigned long long r;
    asm("mov.b64 %0, {%1, %2};" : "=l"(r) : "f"(lo), "f"(hi));
    return r;
}
__device__ __forceinline__ void upk2(unsigned long long v, float& lo, float& hi) {
    asm("mov.b64 {%0, %1}, %2;" : "=f"(lo), "=f"(hi) : "l"(v));
}
__device__ __forceinline__ unsigned long long fma2(unsigned long long a,
                                                   unsigned long long b,
                                                   unsigned long long c) {
    unsigned long long d;
    asm("fma.rn.f32x2 %0, %1, %2, %3;" : "=l"(d) : "l"(a), "l"(b), "l"(c));
    return d;
}
__device__ __forceinline__ float tanha(float x) {
    float y;
    asm("tanh.approx.f32 %0, %1;" : "=f"(y) : "f"(x));
    return y;
}
__device__ __forceinline__ float sig_full(float x) {
    return fmaf(tanha(0.5f * x), 0.5f, 0.5f);
}
__device__ __forceinline__ float getc(float4 v, int i) {
    return i == 0 ? v.x : i == 1 ? v.y : i == 2 ? v.z : v.w;
}

// ---------- TMA / mbarrier helpers ----------
__device__ __forceinline__ uint32_t s2u(const void* p) {
    uint32_t a;
    asm("{ .reg .u64 t; cvta.to.shared.u64 t, %1; cvt.u32.u64 %0, t; }"
        : "=r"(a) : "l"(p));
    return a;
}
__device__ __forceinline__ void mb_init(uint32_t a, uint32_t c) {
    asm volatile("mbarrier.init.shared.b64 [%0], %1;" :: "r"(a), "r"(c) : "memory");
}
__device__ __forceinline__ void mb_expect(uint32_t a, uint32_t bytes) {
    asm volatile("mbarrier.arrive.expect_tx.shared.b64 _, [%0], %1;"
                 :: "r"(a), "r"(bytes) : "memory");
}
__device__ __forceinline__ void mb_wait(uint32_t a, uint32_t par) {
    asm volatile(
        "{\n\t"
        ".reg .pred P;\n\t"
        "WL_%=:\n\t"
        "mbarrier.try_wait.parity.acquire.cta.shared::cta.b64 P, [%0], %1, 0x989680;\n\t"
        "@P bra WD_%=;\n\t"
        "bra WL_%=;\n\t"
        "WD_%=:\n\t"
        "}"
        :: "r"(a), "r"(par) : "memory");
}
__device__ __forceinline__ void bulk_g2s(uint32_t dst, const void* src,
                                         uint32_t bytes, uint32_t mbar) {
    asm volatile(
        "cp.async.bulk.shared::cluster.global.mbarrier::complete_tx::bytes "
        "[%0], [%1], %2, [%3];"
        :: "r"(dst), "l"(src), "r"(bytes), "r"(mbar) : "memory");
}

// ---------- fused persistent kernel: 1 block = 2 batch elements ----------
// warps 0-3: gi producers batch 0 | warps 4-7: producers batch 1
// warp 8: recurrence batch 0      | warp 9: recurrence batch 1
// TMA bulk copies stream x chunks into double-buffered SMEM.
__global__ void __launch_bounds__(320, 1) k_fused(
    const float* __restrict__ x,
    const float* __restrict__ w_ihf, const float* __restrict__ b_ihf,
    const float* __restrict__ w_ihb, const float* __restrict__ b_ihb,
    const float* __restrict__ whh,  const float* __restrict__ bhhf,
    const float* __restrict__ bhhb, const float* __restrict__ wlin,
    const float* __restrict__ blin, float* __restrict__ out)
{
    extern __shared__ unsigned long long sm[];
    unsigned long long* sw = sm;
    ulonglong2* swv = (ulonglong2*)sm;
    char* smc = (char*)sm;
    const uint32_t sbase = s2u(sm);

    const int tid = threadIdx.x;
    const int b0  = blockIdx.x * 2;
    const unsigned m = 0xffffffffu;

    const bool is_rec = (tid >= 256);
    const int bt = is_rec ? ((tid - 256) >> 5) : (tid >> 7);  // batch slot 0/1
    const int b  = b0 + bt;

    if (tid == 0) {
        for (int i = 0; i < 4; ++i) mb_init(sbase + MBOFF_B + 8 * i, 1);
    }

    // ---------- producer setup: stage w_ih_f (rows<20 scaled 0.5) ----------
    const int pt = tid & 127;
    const int d  = pt & 7;     // pair-duo: pairs 2d, 2d+1 (d=7 -> pair 14 only)
    const int r0 = pt >> 3;    // rows r0 and r0+16 of the 32-row chunk
    unsigned long long biasd[2] = {0ULL, 0ULL};

    if (!is_rec) {
        for (int i = tid; i < EMB * 16; i += 256) {
            int k = i >> 4, p = i & 15;
            unsigned long long v = 0ULL;
            if (p < 15) {
                float sc = (p < 10) ? 0.5f : 1.0f;
                v = pk2(sc * __ldg(w_ihf + (2 * p) * EMB + k),
                        sc * __ldg(w_ihf + (2 * p + 1) * EMB + k));
            }
            sw[i] = v;
        }
#pragma unroll
        for (int j = 0; j < 2; ++j) {
            int P = 2 * d + j;
            if (P < 15) {
                float sc = (P < 10) ? 0.5f : 1.0f;
                biasd[j] = pk2(sc * __ldg(b_ihf + 2 * P),
                               sc * __ldg(b_ihf + 2 * P + 1));
            }
        }
    }

    // ---------- rec setup: bwd-dir gi dot + w_hh staging ----------
    const int l   = tid & 31;
    const int l30 = (l < G3) ? l : 0;
    float gb = 0.0f, wv[HID], biasr = 0.0f, h[HID], hown = 0.0f;

    if (is_rec) {
        const float4* xq = (const float4*)(x + ((size_t)b * SEQ + SEQ - 1) * EMB);
        const float4* wq = (const float4*)(w_ihb + (size_t)l30 * EMB);
        float a0 = 0, a1 = 0, a2 = 0, a3 = 0;
#pragma unroll 5
        for (int k4 = 0; k4 < K4C; ++k4) {
            float4 xv = __ldg(xq + k4);
            float4 wv4 = __ldg(wq + k4);
            a0 = fmaf(xv.x, wv4.x, a0);
            a1 = fmaf(xv.y, wv4.y, a1);
            a2 = fmaf(xv.z, wv4.z, a2);
            a3 = fmaf(xv.w, wv4.w, a3);
        }
        gb = (a0 + a1) + (a2 + a3) + ((l < G3) ? __ldg(b_ihb + l) : 0.0f);

        const float scl = (l < 20) ? 0.5f : 1.0f;
#pragma unroll
        for (int k = 0; k < HID; ++k) wv[k] = 0.0f;
        if (l < G3) {
#pragma unroll
            for (int k = 0; k < HID; ++k) wv[k] = scl * __ldg(whh + l * HID + k);
            biasr = scl * __ldg(bhhf + l);
        }
#pragma unroll
        for (int k = 0; k < HID; ++k) h[k] = 0.0f;
    }

    __syncthreads();   // mbarriers initialized + weights staged

    // ---------- 3-stage phase pipeline ----------
    for (int p = 0; p <= NCH + 1; ++p) {
        // stage A: issue TMA for x chunk p (both batches)
        if (tid == 0 && p < NCH) {
            int slot = p & 1;
#pragma unroll
            for (int t2 = 0; t2 < 2; ++t2) {
                uint32_t mb = sbase + MBOFF_B + 8 * (t2 * 2 + slot);
                mb_expect(mb, XTILE_B);
                bulk_g2s(sbase + XOFF_B + (t2 * 2 + slot) * XTILE_B,
                         x + ((size_t)(b0 + t2) * SEQ + (size_t)p * CHUNK) * EMB,
                         XTILE_B, mb);
            }
        }

        // stage B: producers compute gi for chunk p-1
        if (!is_rec && p >= 1 && p <= NCH) {
            const int c = p - 1, slot = c & 1;
            mb_wait(sbase + MBOFF_B + 8 * (bt * 2 + slot),
                    (uint32_t)((c >> 1) & 1));

            const float* xb = (const float*)(smc + XOFF_B + (bt * 2 + slot) * XTILE_B);
            float* go = (float*)(smc + GIOFF_B + (bt * 2 + slot) * GI_B);

            unsigned long long acc[2][2];
            acc[0][0] = biasd[0]; acc[0][1] = biasd[1];
            acc[1][0] = biasd[0]; acc[1][1] = biasd[1];

            const float4* xr0 = (const float4*)(xb + r0 * EMB);
            const float4* xr1 = (const float4*)(xb + (r0 + 16) * EMB);

#pragma unroll 3
            for (int k4 = 0; k4 < K4C; ++k4) {
                float4 x0 = xr0[k4];
                float4 x1 = xr1[k4];
#pragma unroll
                for (int kk = 0; kk < 4; ++kk) {
                    ulonglong2 wq = swv[(4 * k4 + kk) * 8 + d];
                    float s0 = getc(x0, kk), s1 = getc(x1, kk);
                    unsigned long long xx0 = pk2(s0, s0);
                    unsigned long long xx1 = pk2(s1, s1);
                    acc[0][0] = fma2(xx0, wq.x, acc[0][0]);
                    acc[0][1] = fma2(xx0, wq.y, acc[0][1]);
                    acc[1][0] = fma2(xx1, wq.x, acc[1][0]);
                    acc[1][1] = fma2(xx1, wq.y, acc[1][1]);
                }
            }

#pragma unroll
            for (int j = 0; j < 2; ++j) {
                float* gr = go + (r0 + 16 * j) * 32;
                float l0, h0, l1, h1;
                upk2(acc[j][0], l0, h0);
                upk2(acc[j][1], l1, h1);
                if (d < 7) *(float4*)(gr + 4 * d) = make_float4(l0, h0, l1, h1);
                else       *(float2*)(gr + 28)    = make_float2(l0, h0);
            }
        }

        // stage C: consumer runs chunk p-2
        if (is_rec && p >= 2) {
            const int c = p - 2, slot = c & 1;
            const float* gi_s = (const float*)(smc + GIOFF_B + (bt * 2 + slot) * GI_B);
            float gcur = gi_s[l30];
#pragma unroll 4
            for (int u = 0; u < CHUNK; ++u) {
                int un = (u + 1 < CHUNK) ? u + 1 : u;
                float gnext = gi_s[un * 32 + l30];

                float inn = __shfl_sync(m, gcur, l + 20);

                float a0 = biasr, a1 = 0.0f, a2 = 0.0f, a3 = 0.0f;
                a0 = fmaf(h[0], wv[0], a0);  a1 = fmaf(h[1], wv[1], a1);
                a2 = fmaf(h[2], wv[2], a2);  a3 = fmaf(h[3], wv[3], a3);
                a0 = fmaf(h[4], wv[4], a0);  a1 = fmaf(h[5], wv[5], a1);
                a2 = fmaf(h[6], wv[6], a2);  a3 = fmaf(h[7], wv[7], a3);
                a0 = fmaf(h[8], wv[8], a0);  a1 = fmaf(h[9], wv[9], a1);
                float gh = (a0 + a1) + (a2 + a3);
                float s  = gcur + gh;

                float t   = tanha(s);
                float ghn = __shfl_sync(m, gh, l + 20);
                float tz  = __shfl_sync(m, t,  l + 10);

                float r  = fmaf(t,  0.5f, 0.5f);
                float z  = fmaf(tz, 0.5f, 0.5f);
                float n  = tanha(fmaf(r, ghn, inn));
                float hn = fmaf(z, hown - n, n);

#pragma unroll
                for (int k = 0; k < HID; ++k) h[k] = __shfl_sync(m, hn, k);
                hown = hn;
                gcur = gnext;
            }
        }

        __syncthreads();
    }

    // ---------- epilogue: backward single step + linear head ----------
    if (is_rec) {
        float bb  = (l < G3) ? __ldg(bhhb + l) : 0.0f;
        float sb  = gb + bb;
        float azb = __shfl_sync(m, sb, l + 10);
        float gbn = __shfl_sync(m, gb, l + 20);
        float bbn = __shfl_sync(m, bb, l + 20);
        float rb  = sig_full(sb);
        float zb  = sig_full(azb);
        float nb  = tanha(fmaf(rb, bbn, gbn));
        float hbv = (1.0f - zb) * nb;

        float cacc = 0.0f;
        if (l < HID) cacc = __ldg(wlin + l) * hown + __ldg(wlin + HID + l) * hbv;
        cacc += __shfl_down_sync(m, cacc, 8);
        cacc += __shfl_down_sync(m, cacc, 4);
        cacc += __shfl_down_sync(m, cacc, 2);
        cacc += __shfl_down_sync(m, cacc, 1);
        if (l == 0) out[b] = cacc + __ldg(blin);
    }
}

extern "C" void kernel_launch(void* const* d_in, const int* in_sizes, int n_in,
                              void* d_out, int out_size)
{
    const float* x      = (const float*)d_in[0];
    const float* w_ih_f = (const float*)d_in[1];
    const float* w_hh_f = (const float*)d_in[2];
    const float* b_ih_f = (const float*)d_in[3];
    const float* b_hh_f = (const float*)d_in[4];
    const float* w_ih_b = (const float*)d_in[5];
    /* w_hh_b (d_in[6]) mathematically unused: h0 = 0 for the single bwd step */
    const float* b_ih_b = (const float*)d_in[7];
    const float* b_hh_b = (const float*)d_in[8];
    const float* w_lin  = (const float*)d_in[9];
    const float* b_lin  = (const float*)d_in[10];
    float* out = (float*)d_out;

    cudaFuncSetAttribute(k_fused, cudaFuncAttributeMaxDynamicSharedMemorySize,
                         SMEM_B);
    k_fused<<<BATCH / 2, 320, SMEM_B>>>(x, w_ih_f, b_ih_f, w_ih_b, b_ih_b,
                                        w_hh_f, b_hh_f, b_hh_b, w_lin, b_lin,
                                        out);
}

// round 6
// speedup vs baseline: 2.9359x; 1.2028x over previous
#include <cuda_runtime.h>
#include <cuda_fp16.h>
#include <cstdint>

#define SEQ 512
#define BATCH 256
#define EMB 300
#define HID 10
#define G3 30
#define K4C 75
#define CHUNK 32
#define NCH (SEQ / CHUNK)            // 16
#define XTILE_B (CHUNK * EMB * 4)    // 38400 B per x chunk
#define GI_B (CHUNK * 32 * 4)        // 4096 B per gi chunk

// byte offsets in dynamic SMEM
#define XOFF_B   0
#define GIOFF_B  (4 * XTILE_B)              // 153600
#define WAOFF_B  (GIOFF_B + 4 * GI_B)       // 169984 (600 uint4)
#define WBOFF_B  (WAOFF_B + 9600)           // 179584 (600 uint4)
#define MBOFF_B  (WBOFF_B + 9600)           // 189184
#define SMEM_B   (MBOFF_B + 64)             // 189248

// packed fp16 weights: [0..599]=A (gates 4d,4d+1), [600..1199]=B (4d+2,4d+3)
__device__ uint4 g_whalf[1200];

// ---------- scalar helpers ----------
__device__ __forceinline__ unsigned long long pk2(float lo, float hi) {
    unsigned long long r;
    asm("mov.b64 %0, {%1, %2};" : "=l"(r) : "f"(lo), "f"(hi));
    return r;
}
__device__ __forceinline__ void upk2(unsigned long long v, float& lo, float& hi) {
    asm("mov.b64 {%0, %1}, %2;" : "=f"(lo), "=f"(hi) : "l"(v));
}
__device__ __forceinline__ unsigned long long fma2(unsigned long long a,
                                                   unsigned long long b,
                                                   unsigned long long c) {
    unsigned long long d;
    asm("fma.rn.f32x2 %0, %1, %2, %3;" : "=l"(d) : "l"(a), "l"(b), "l"(c));
    return d;
}
__device__ __forceinline__ float tanha(float x) {
    float y;
    asm("tanh.approx.f32 %0, %1;" : "=f"(y) : "f"(x));
    return y;
}
__device__ __forceinline__ float sig_full(float x) {
    return fmaf(tanha(0.5f * x), 0.5f, 0.5f);
}
__device__ __forceinline__ float getc(float4 v, int i) {
    return i == 0 ? v.x : i == 1 ? v.y : i == 2 ? v.z : v.w;
}
__device__ __forceinline__ unsigned long long h2w(__half2 h) {
    float2 f = __half22float2(h);
    return pk2(f.x, f.y);
}

// ---------- TMA / mbarrier helpers ----------
__device__ __forceinline__ uint32_t s2u(const void* p) {
    uint32_t a;
    asm("{ .reg .u64 t; cvta.to.shared.u64 t, %1; cvt.u32.u64 %0, t; }"
        : "=r"(a) : "l"(p));
    return a;
}
__device__ __forceinline__ void mb_init(uint32_t a, uint32_t c) {
    asm volatile("mbarrier.init.shared.b64 [%0], %1;" :: "r"(a), "r"(c) : "memory");
}
__device__ __forceinline__ void mb_expect(uint32_t a, uint32_t bytes) {
    asm volatile("mbarrier.arrive.expect_tx.shared.b64 _, [%0], %1;"
                 :: "r"(a), "r"(bytes) : "memory");
}
__device__ __forceinline__ void mb_wait(uint32_t a, uint32_t par) {
    asm volatile(
        "{\n\t"
        ".reg .pred P;\n\t"
        "WL_%=:\n\t"
        "mbarrier.try_wait.parity.acquire.cta.shared::cta.b64 P, [%0], %1, 0x989680;\n\t"
        "@P bra WD_%=;\n\t"
        "bra WL_%=;\n\t"
        "WD_%=:\n\t"
        "}"
        :: "r"(a), "r"(par) : "memory");
}
__device__ __forceinline__ void bulk_g2s(uint32_t dst, const void* src,
                                         uint32_t bytes, uint32_t mbar) {
    asm volatile(
        "cp.async.bulk.shared::cluster.global.mbarrier::complete_tx::bytes "
        "[%0], [%1], %2, [%3];"
        :: "r"(dst), "l"(src), "r"(bytes), "r"(mbar) : "memory");
}

// ---------- prep: pack w_ih_f into fp16 (gates<20 pre-scaled by 0.5) -------
__global__ void k_prep(const float* __restrict__ w) {
    int e = blockIdx.x * blockDim.x + threadIdx.x;   // 0..599
    if (e >= 600) return;
    int k4 = e >> 3, d = e & 7;
#pragma unroll
    for (int grp = 0; grp < 2; ++grp) {              // A: gates 4d..4d+1, B: +2..3
        int g0 = 4 * d + 2 * grp;
        uint4 u;
        __half2* h = (__half2*)&u;
#pragma unroll
        for (int kk = 0; kk < 4; ++kk) {
            int k = 4 * k4 + kk;
            float w0 = 0.0f, w1 = 0.0f;
            if (g0 < G3)     w0 = ((g0 < 20)     ? 0.5f : 1.0f) * w[g0 * EMB + k];
            if (g0 + 1 < G3) w1 = ((g0 + 1 < 20) ? 0.5f : 1.0f) * w[(g0 + 1) * EMB + k];
            h[kk] = __floats2half2_rn(w0, w1);
        }
        g_whalf[grp * 600 + e] = u;
    }
}

// ---------- fused kernel: 1 block = 2 batch elements, 192 threads ----------
// warps 0-3: producers (warp w: batch w>>1, row-half w&1), R=4 rows, P=2 pairs
// warps 4-5: recurrence consumers (batch 0 / 1)
__global__ void __launch_bounds__(192, 1) k_fused(
    const float* __restrict__ x,
    const float* __restrict__ b_ihf,
    const float* __restrict__ w_ihb, const float* __restrict__ b_ihb,
    const float* __restrict__ whh,  const float* __restrict__ bhhf,
    const float* __restrict__ bhhb, const float* __restrict__ wlin,
    const float* __restrict__ blin, float* __restrict__ out)
{
    extern __shared__ char smc[];
    const uint32_t sbase = s2u(smc);
    uint4* swA = (uint4*)(smc + WAOFF_B);
    uint4* swB = (uint4*)(smc + WBOFF_B);

    const int tid = threadIdx.x;
    const int b0  = blockIdx.x * 2;
    const unsigned m = 0xffffffffu;

    const bool is_rec = (tid >= 128);
    const int bt = is_rec ? ((tid - 128) >> 5) : (tid >> 6);  // batch slot
    const int b  = b0 + bt;

    if (tid == 0)
        for (int i = 0; i < 4; ++i) mb_init(sbase + MBOFF_B + 8 * i, 1);

    // ---------- producer setup ----------
    const int lane = tid & 31;
    const int hf = (tid >> 5) & 1;      // row-half within chunk (warps 0-3)
    const int d  = lane & 7;            // gate-duo: gates 4d..4d+3
    const int rg = lane >> 3;           // row-group
    const int r0 = hf * 16 + rg * 4;    // rows r0..r0+3 of the 32-row chunk
    unsigned long long biasA = 0ULL, biasB = 0ULL;

    if (!is_rec) {
        // stage packed fp16 weights into SMEM (19.2 KB)
        for (int i = tid; i < 1200; i += 128)
            ((uint4*)(smc + WAOFF_B))[i] = g_whalf[i];
        {
            int g0 = 4 * d;
            float s0 = (g0 < 20) ? 0.5f : 1.0f;
            float s1 = (g0 + 1 < 20) ? 0.5f : 1.0f;
            biasA = pk2(s0 * __ldg(b_ihf + g0), s1 * __ldg(b_ihf + g0 + 1));
            if (g0 + 3 < G3) {
                float s2 = (g0 + 2 < 20) ? 0.5f : 1.0f;
                biasB = pk2(s2 * __ldg(b_ihf + g0 + 2),
                            1.0f * __ldg(b_ihf + g0 + 3) * ((g0 + 3 < 20) ? 0.5f : 1.0f) /
                            ((g0 + 3 < 20) ? 1.0f : 1.0f));
                // simpler exact form:
                float v2 = ((g0 + 2 < 20) ? 0.5f : 1.0f) * __ldg(b_ihf + g0 + 2);
                float v3 = ((g0 + 3 < 20) ? 0.5f : 1.0f) * __ldg(b_ihf + g0 + 3);
                biasB = pk2(v2, v3);
            }
        }
    }

    // ---------- rec setup: bwd-dir gi dot + w_hh staging ----------
    const int l   = lane;
    const int l30 = (l < G3) ? l : 0;
    float gb = 0.0f, wv[HID], biasr = 0.0f, h[HID], hown = 0.0f;

    if (is_rec) {
        const float4* xq = (const float4*)(x + ((size_t)b * SEQ + SEQ - 1) * EMB);
        const float4* wq = (const float4*)(w_ihb + (size_t)l30 * EMB);
        float a0 = 0, a1 = 0, a2 = 0, a3 = 0;
#pragma unroll 5
        for (int k4 = 0; k4 < K4C; ++k4) {
            float4 xv = __ldg(xq + k4);
            float4 wv4 = __ldg(wq + k4);
            a0 = fmaf(xv.x, wv4.x, a0);
            a1 = fmaf(xv.y, wv4.y, a1);
            a2 = fmaf(xv.z, wv4.z, a2);
            a3 = fmaf(xv.w, wv4.w, a3);
        }
        gb = (a0 + a1) + (a2 + a3) + ((l < G3) ? __ldg(b_ihb + l) : 0.0f);

        const float scl = (l < 20) ? 0.5f : 1.0f;
#pragma unroll
        for (int k = 0; k < HID; ++k) wv[k] = 0.0f;
        if (l < G3) {
#pragma unroll
            for (int k = 0; k < HID; ++k) wv[k] = scl * __ldg(whh + l * HID + k);
            biasr = scl * __ldg(bhhf + l);
        }
#pragma unroll
        for (int k = 0; k < HID; ++k) h[k] = 0.0f;
    }

    __syncthreads();   // mbarriers + weights staged

    // ---------- 3-stage lockstep pipeline ----------
    for (int p = 0; p <= NCH + 1; ++p) {
        // stage A: TMA x chunk p for both batches
        if (tid == 0 && p < NCH) {
            int slot = p & 1;
#pragma unroll
            for (int t2 = 0; t2 < 2; ++t2) {
                uint32_t mb = sbase + MBOFF_B + 8 * (t2 * 2 + slot);
                mb_expect(mb, XTILE_B);
                bulk_g2s(sbase + XOFF_B + (t2 * 2 + slot) * XTILE_B,
                         x + ((size_t)(b0 + t2) * SEQ + (size_t)p * CHUNK) * EMB,
                         XTILE_B, mb);
            }
        }

        // stage B: producers compute gi chunk p-1
        if (!is_rec && p >= 1 && p <= NCH) {
            const int c = p - 1, slot = c & 1;
            mb_wait(sbase + MBOFF_B + 8 * (bt * 2 + slot),
                    (uint32_t)((c >> 1) & 1));

            const float* xb = (const float*)(smc + XOFF_B + (bt * 2 + slot) * XTILE_B);
            float* go = (float*)(smc + GIOFF_B + (bt * 2 + slot) * GI_B);

            unsigned long long accA[4], accB[4];
#pragma unroll
            for (int j = 0; j < 4; ++j) { accA[j] = biasA; accB[j] = biasB; }

            const float4* xr = (const float4*)(xb + r0 * EMB);

#pragma unroll 3
            for (int k4 = 0; k4 < K4C; ++k4) {
                uint4 wa = swA[k4 * 8 + d];
                uint4 wb = swB[k4 * 8 + d];
                float4 xv[4];
#pragma unroll
                for (int j = 0; j < 4; ++j) xv[j] = xr[j * K4C + k4];
#pragma unroll
                for (int kk = 0; kk < 4; ++kk) {
                    unsigned long long wA = h2w(((__half2*)&wa)[kk]);
                    unsigned long long wB = h2w(((__half2*)&wb)[kk]);
#pragma unroll
                    for (int j = 0; j < 4; ++j) {
                        float xs = getc(xv[j], kk);
                        unsigned long long xx = pk2(xs, xs);
                        accA[j] = fma2(xx, wA, accA[j]);
                        accB[j] = fma2(xx, wB, accB[j]);
                    }
                }
            }

#pragma unroll
            for (int j = 0; j < 4; ++j) {
                float a0, a1, b0f, b1f;
                upk2(accA[j], a0, a1);
                upk2(accB[j], b0f, b1f);
                *(float4*)(go + (r0 + j) * 32 + 4 * d) = make_float4(a0, a1, b0f, b1f);
            }
        }

        // stage C: consumer runs chunk p-2
        if (is_rec && p >= 2) {
            const int c = p - 2, slot = c & 1;
            const float* gi_s = (const float*)(smc + GIOFF_B + (bt * 2 + slot) * GI_B);
            float gcur = gi_s[l30];
#pragma unroll 4
            for (int u = 0; u < CHUNK; ++u) {
                int un = (u + 1 < CHUNK) ? u + 1 : u;
                float gnext = gi_s[un * 32 + l30];

                float inn = __shfl_sync(m, gcur, l + 20);

                float a0 = biasr, a1 = 0.0f, a2 = 0.0f, a3 = 0.0f;
                a0 = fmaf(h[0], wv[0], a0);  a1 = fmaf(h[1], wv[1], a1);
                a2 = fmaf(h[2], wv[2], a2);  a3 = fmaf(h[3], wv[3], a3);
                a0 = fmaf(h[4], wv[4], a0);  a1 = fmaf(h[5], wv[5], a1);
                a2 = fmaf(h[6], wv[6], a2);  a3 = fmaf(h[7], wv[7], a3);
                a0 = fmaf(h[8], wv[8], a0);  a1 = fmaf(h[9], wv[9], a1);
                float gh = (a0 + a1) + (a2 + a3);
                float s  = gcur + gh;

                float t   = tanha(s);
                float ghn = __shfl_sync(m, gh, l + 20);
                float tz  = __shfl_sync(m, t,  l + 10);

                float r  = fmaf(t,  0.5f, 0.5f);
                float z  = fmaf(tz, 0.5f, 0.5f);
                float n  = tanha(fmaf(r, ghn, inn));
                float hn = fmaf(z, hown - n, n);

#pragma unroll
                for (int k = 0; k < HID; ++k) h[k] = __shfl_sync(m, hn, k);
                hown = hn;
                gcur = gnext;
            }
        }

        __syncthreads();
    }

    // ---------- epilogue: backward single step + linear head ----------
    if (is_rec) {
        float bb  = (l < G3) ? __ldg(bhhb + l) : 0.0f;
        float sb  = gb + bb;
        float azb = __shfl_sync(m, sb, l + 10);
        float gbn = __shfl_sync(m, gb, l + 20);
        float bbn = __shfl_sync(m, bb, l + 20);
        float rb  = sig_full(sb);
        float zb  = sig_full(azb);
        float nb  = tanha(fmaf(rb, bbn, gbn));
        float hbv = (1.0f - zb) * nb;

        float cacc = 0.0f;
        if (l < HID) cacc = __ldg(wlin + l) * hown + __ldg(wlin + HID + l) * hbv;
        cacc += __shfl_down_sync(m, cacc, 8);
        cacc += __shfl_down_sync(m, cacc, 4);
        cacc += __shfl_down_sync(m, cacc, 2);
        cacc += __shfl_down_sync(m, cacc, 1);
        if (l == 0) out[b] = cacc + __ldg(blin);
    }
}

extern "C" void kernel_launch(void* const* d_in, const int* in_sizes, int n_in,
                              void* d_out, int out_size)
{
    const float* x      = (const float*)d_in[0];
    const float* w_ih_f = (const float*)d_in[1];
    const float* w_hh_f = (const float*)d_in[2];
    const float* b_ih_f = (const float*)d_in[3];
    const float* b_hh_f = (const float*)d_in[4];
    const float* w_ih_b = (const float*)d_in[5];
    /* w_hh_b (d_in[6]) mathematically unused: h0 = 0 for the single bwd step */
    const float* b_ih_b = (const float*)d_in[7];
    const float* b_hh_b = (const float*)d_in[8];
    const float* w_lin  = (const float*)d_in[9];
    const float* b_lin  = (const float*)d_in[10];
    float* out = (float*)d_out;

    k_prep<<<5, 128>>>(w_ih_f);

    cudaFuncSetAttribute(k_fused, cudaFuncAttributeMaxDynamicSharedMemorySize,
                         SMEM_B);
    k_fused<<<BATCH / 2, 192, SMEM_B>>>(x, b_ih_f, w_ih_b, b_ih_b,
                                        w_hh_f, b_hh_f, b_hh_b, w_lin, b_lin,
                                        out);
}

// round 7
// speedup vs baseline: 2.9392x; 1.0011x over previous
#include <cuda_runtime.h>
#include <cuda_fp16.h>
#include <cstdint>

#define SEQ 512
#define BATCH 256
#define EMB 300
#define HID 10
#define G3 30
#define K4C 75
#define CHUNK 32
#define NCH (SEQ / CHUNK)            // 16
#define XTILE_B (CHUNK * EMB * 4)    // 38400 B per x chunk
#define GI_B (CHUNK * 32 * 4)        // 4096 B per gi chunk

// byte offsets in dynamic SMEM
#define XOFF_B   0
#define GIOFF_B  (4 * XTILE_B)              // 153600
#define WAOFF_B  (GIOFF_B + 4 * GI_B)       // 169984 (600 uint4)
#define WBOFF_B  (WAOFF_B + 9600)           // 179584 (600 uint4)
#define MBOFF_B  (WBOFF_B + 9600)           // 189184
#define SMEM_B   (MBOFF_B + 64)             // 189248

// packed fp16 weights: [0..599]=A (gates 4d,4d+1), [600..1199]=B (4d+2,4d+3)
__device__ uint4 g_whalf[1200];

// ---------- scalar helpers ----------
__device__ __forceinline__ unsigned long long pk2(float lo, float hi) {
    unsigned long long r;
    asm("mov.b64 %0, {%1, %2};" : "=l"(r) : "f"(lo), "f"(hi));
    return r;
}
__device__ __forceinline__ void upk2(unsigned long long v, float& lo, float& hi) {
    asm("mov.b64 {%0, %1}, %2;" : "=f"(lo), "=f"(hi) : "l"(v));
}
__device__ __forceinline__ unsigned long long fma2(unsigned long long a,
                                                   unsigned long long b,
                                                   unsigned long long c) {
    unsigned long long d;
    asm("fma.rn.f32x2 %0, %1, %2, %3;" : "=l"(d) : "l"(a), "l"(b), "l"(c));
    return d;
}
__device__ __forceinline__ float tanha(float x) {
    float y;
    asm("tanh.approx.f32 %0, %1;" : "=f"(y) : "f"(x));
    return y;
}
__device__ __forceinline__ float sig_full(float x) {
    return fmaf(tanha(0.5f * x), 0.5f, 0.5f);
}
__device__ __forceinline__ float getc(float4 v, int i) {
    return i == 0 ? v.x : i == 1 ? v.y : i == 2 ? v.z : v.w;
}
__device__ __forceinline__ unsigned long long h2w(__half2 h) {
    float2 f = __half22float2(h);
    return pk2(f.x, f.y);
}

// ---------- TMA / mbarrier helpers ----------
__device__ __forceinline__ uint32_t s2u(const void* p) {
    uint32_t a;
    asm("{ .reg .u64 t; cvta.to.shared.u64 t, %1; cvt.u32.u64 %0, t; }"
        : "=r"(a) : "l"(p));
    return a;
}
__device__ __forceinline__ void mb_init(uint32_t a, uint32_t c) {
    asm volatile("mbarrier.init.shared.b64 [%0], %1;" :: "r"(a), "r"(c) : "memory");
}
__device__ __forceinline__ void mb_expect(uint32_t a, uint32_t bytes) {
    asm volatile("mbarrier.arrive.expect_tx.shared.b64 _, [%0], %1;"
                 :: "r"(a), "r"(bytes) : "memory");
}
__device__ __forceinline__ void mb_wait(uint32_t a, uint32_t par) {
    asm volatile(
        "{\n\t"
        ".reg .pred P;\n\t"
        "WL_%=:\n\t"
        "mbarrier.try_wait.parity.acquire.cta.shared::cta.b64 P, [%0], %1, 0x989680;\n\t"
        "@P bra WD_%=;\n\t"
        "bra WL_%=;\n\t"
        "WD_%=:\n\t"
        "}"
        :: "r"(a), "r"(par) : "memory");
}
__device__ __forceinline__ void bulk_g2s(uint32_t dst, const void* src,
                                         uint32_t bytes, uint32_t mbar) {
    asm volatile(
        "cp.async.bulk.shared::cluster.global.mbarrier::complete_tx::bytes "
        "[%0], [%1], %2, [%3];"
        :: "r"(dst), "l"(src), "r"(bytes), "r"(mbar) : "memory");
}

// ---------- prep: pack w_ih_f into fp16 (gates<20 pre-scaled by 0.5) -------
__global__ void k_prep(const float* __restrict__ w) {
    int e = blockIdx.x * blockDim.x + threadIdx.x;   // 0..599
    if (e >= 600) return;
    int k4 = e >> 3, d = e & 7;
#pragma unroll
    for (int grp = 0; grp < 2; ++grp) {              // A: gates 4d..4d+1, B: +2..3
        int g0 = 4 * d + 2 * grp;
        uint4 u;
        __half2* h = (__half2*)&u;
#pragma unroll
        for (int kk = 0; kk < 4; ++kk) {
            int k = 4 * k4 + kk;
            float w0 = 0.0f, w1 = 0.0f;
            if (g0 < G3)     w0 = ((g0 < 20)     ? 0.5f : 1.0f) * w[g0 * EMB + k];
            if (g0 + 1 < G3) w1 = ((g0 + 1 < 20) ? 0.5f : 1.0f) * w[(g0 + 1) * EMB + k];
            h[kk] = __floats2half2_rn(w0, w1);
        }
        g_whalf[grp * 600 + e] = u;
    }
}

// ---------- fused kernel: 1 block = 2 batch elements, 192 threads ----------
// warps 0-3: producers (warp w: batch w>>1, row-half w&1), R=4 rows, P=2 pairs
// warps 4-5: recurrence consumers (batch 0 / 1)
__global__ void __launch_bounds__(192, 1) k_fused(
    const float* __restrict__ x,
    const float* __restrict__ b_ihf,
    const float* __restrict__ w_ihb, const float* __restrict__ b_ihb,
    const float* __restrict__ whh,  const float* __restrict__ bhhf,
    const float* __restrict__ bhhb, const float* __restrict__ wlin,
    const float* __restrict__ blin, float* __restrict__ out)
{
    extern __shared__ char smc[];
    const uint32_t sbase = s2u(smc);
    uint4* swA = (uint4*)(smc + WAOFF_B);
    uint4* swB = (uint4*)(smc + WBOFF_B);

    const int tid = threadIdx.x;
    const int b0  = blockIdx.x * 2;
    const unsigned m = 0xffffffffu;

    const bool is_rec = (tid >= 128);
    const int bt = is_rec ? ((tid - 128) >> 5) : (tid >> 6);  // batch slot
    const int b  = b0 + bt;

    if (tid == 0)
        for (int i = 0; i < 4; ++i) mb_init(sbase + MBOFF_B + 8 * i, 1);

    // ---------- producer setup ----------
    const int lane = tid & 31;
    const int hf = (tid >> 5) & 1;      // row-half within chunk (warps 0-3)
    const int d  = lane & 7;            // gate-duo: gates 4d..4d+3
    const int rg = lane >> 3;           // row-group
    const int r0 = hf * 16 + rg * 4;    // rows r0..r0+3 of the 32-row chunk
    unsigned long long biasA = 0ULL, biasB = 0ULL;

    if (!is_rec) {
        // stage packed fp16 weights into SMEM (19.2 KB)
        for (int i = tid; i < 1200; i += 128)
            ((uint4*)(smc + WAOFF_B))[i] = g_whalf[i];
        {
            int g0 = 4 * d;
            float s0 = (g0 < 20) ? 0.5f : 1.0f;
            float s1 = (g0 + 1 < 20) ? 0.5f : 1.0f;
            biasA = pk2(s0 * __ldg(b_ihf + g0), s1 * __ldg(b_ihf + g0 + 1));
            if (g0 + 3 < G3) {
                float s2 = (g0 + 2 < 20) ? 0.5f : 1.0f;
                biasB = pk2(s2 * __ldg(b_ihf + g0 + 2),
                            1.0f * __ldg(b_ihf + g0 + 3) * ((g0 + 3 < 20) ? 0.5f : 1.0f) /
                            ((g0 + 3 < 20) ? 1.0f : 1.0f));
                // simpler exact form:
                float v2 = ((g0 + 2 < 20) ? 0.5f : 1.0f) * __ldg(b_ihf + g0 + 2);
                float v3 = ((g0 + 3 < 20) ? 0.5f : 1.0f) * __ldg(b_ihf + g0 + 3);
                biasB = pk2(v2, v3);
            }
        }
    }

    // ---------- rec setup: bwd-dir gi dot + w_hh staging ----------
    const int l   = lane;
    const int l30 = (l < G3) ? l : 0;
    float gb = 0.0f, wv[HID], biasr = 0.0f, h[HID], hown = 0.0f;

    if (is_rec) {
        const float4* xq = (const float4*)(x + ((size_t)b * SEQ + SEQ - 1) * EMB);
        const float4* wq = (const float4*)(w_ihb + (size_t)l30 * EMB);
        float a0 = 0, a1 = 0, a2 = 0, a3 = 0;
#pragma unroll 5
        for (int k4 = 0; k4 < K4C; ++k4) {
            float4 xv = __ldg(xq + k4);
            float4 wv4 = __ldg(wq + k4);
            a0 = fmaf(xv.x, wv4.x, a0);
            a1 = fmaf(xv.y, wv4.y, a1);
            a2 = fmaf(xv.z, wv4.z, a2);
            a3 = fmaf(xv.w, wv4.w, a3);
        }
        gb = (a0 + a1) + (a2 + a3) + ((l < G3) ? __ldg(b_ihb + l) : 0.0f);

        const float scl = (l < 20) ? 0.5f : 1.0f;
#pragma unroll
        for (int k = 0; k < HID; ++k) wv[k] = 0.0f;
        if (l < G3) {
#pragma unroll
            for (int k = 0; k < HID; ++k) wv[k] = scl * __ldg(whh + l * HID + k);
            biasr = scl * __ldg(bhhf + l);
        }
#pragma unroll
        for (int k = 0; k < HID; ++k) h[k] = 0.0f;
    }

    __syncthreads();   // mbarriers + weights staged

    // ---------- 3-stage lockstep pipeline ----------
    for (int p = 0; p <= NCH + 1; ++p) {
        // stage A: TMA x chunk p for both batches
        if (tid == 0 && p < NCH) {
            int slot = p & 1;
#pragma unroll
            for (int t2 = 0; t2 < 2; ++t2) {
                uint32_t mb = sbase + MBOFF_B + 8 * (t2 * 2 + slot);
                mb_expect(mb, XTILE_B);
                bulk_g2s(sbase + XOFF_B + (t2 * 2 + slot) * XTILE_B,
                         x + ((size_t)(b0 + t2) * SEQ + (size_t)p * CHUNK) * EMB,
                         XTILE_B, mb);
            }
        }

        // stage B: producers compute gi chunk p-1
        if (!is_rec && p >= 1 && p <= NCH) {
            const int c = p - 1, slot = c & 1;
            mb_wait(sbase + MBOFF_B + 8 * (bt * 2 + slot),
                    (uint32_t)((c >> 1) & 1));

            const float* xb = (const float*)(smc + XOFF_B + (bt * 2 + slot) * XTILE_B);
            float* go = (float*)(smc + GIOFF_B + (bt * 2 + slot) * GI_B);

            unsigned long long accA[4], accB[4];
#pragma unroll
            for (int j = 0; j < 4; ++j) { accA[j] = biasA; accB[j] = biasB; }

            const float4* xr = (const float4*)(xb + r0 * EMB);

#pragma unroll 3
            for (int k4 = 0; k4 < K4C; ++k4) {
                uint4 wa = swA[k4 * 8 + d];
                uint4 wb = swB[k4 * 8 + d];
                float4 xv[4];
#pragma unroll
                for (int j = 0; j < 4; ++j) xv[j] = xr[j * K4C + k4];
#pragma unroll
                for (int kk = 0; kk < 4; ++kk) {
                    unsigned long long wA = h2w(((__half2*)&wa)[kk]);
                    unsigned long long wB = h2w(((__half2*)&wb)[kk]);
#pragma unroll
                    for (int j = 0; j < 4; ++j) {
                        float xs = getc(xv[j], kk);
                        unsigned long long xx = pk2(xs, xs);
                        accA[j] = fma2(xx, wA, accA[j]);
                        accB[j] = fma2(xx, wB, accB[j]);
                    }
                }
            }

#pragma unroll
            for (int j = 0; j < 4; ++j) {
                float a0, a1, b0f, b1f;
                upk2(accA[j], a0, a1);
                upk2(accB[j], b0f, b1f);
                *(float4*)(go + (r0 + j) * 32 + 4 * d) = make_float4(a0, a1, b0f, b1f);
            }
        }

        // stage C: consumer runs chunk p-2
        if (is_rec && p >= 2) {
            const int c = p - 2, slot = c & 1;
            const float* gi_s = (const float*)(smc + GIOFF_B + (bt * 2 + slot) * GI_B);
            float gcur = gi_s[l30];
#pragma unroll 4
            for (int u = 0; u < CHUNK; ++u) {
                int un = (u + 1 < CHUNK) ? u + 1 : u;
                float gnext = gi_s[un * 32 + l30];

                float inn = __shfl_sync(m, gcur, l + 20);

                float a0 = biasr, a1 = 0.0f, a2 = 0.0f, a3 = 0.0f;
                a0 = fmaf(h[0], wv[0], a0);  a1 = fmaf(h[1], wv[1], a1);
                a2 = fmaf(h[2], wv[2], a2);  a3 = fmaf(h[3], wv[3], a3);
                a0 = fmaf(h[4], wv[4], a0);  a1 = fmaf(h[5], wv[5], a1);
                a2 = fmaf(h[6], wv[6], a2);  a3 = fmaf(h[7], wv[7], a3);
                a0 = fmaf(h[8], wv[8], a0);  a1 = fmaf(h[9], wv[9], a1);
                float gh = (a0 + a1) + (a2 + a3);
                float s  = gcur + gh;

                float t   = tanha(s);
                float ghn = __shfl_sync(m, gh, l + 20);
                float tz  = __shfl_sync(m, t,  l + 10);

                float r  = fmaf(t,  0.5f, 0.5f);
                float z  = fmaf(tz, 0.5f, 0.5f);
                float n  = tanha(fmaf(r, ghn, inn));
                float hn = fmaf(z, hown - n, n);

#pragma unroll
                for (int k = 0; k < HID; ++k) h[k] = __shfl_sync(m, hn, k);
                hown = hn;
                gcur = gnext;
            }
        }

        __syncthreads();
    }

    // ---------- epilogue: backward single step + linear head ----------
    if (is_rec) {
        float bb  = (l < G3) ? __ldg(bhhb + l) : 0.0f;
        float sb  = gb + bb;
        float azb = __shfl_sync(m, sb, l + 10);
        float gbn = __shfl_sync(m, gb, l + 20);
        float bbn = __shfl_sync(m, bb, l + 20);
        float rb  = sig_full(sb);
        float zb  = sig_full(azb);
        float nb  = tanha(fmaf(rb, bbn, gbn));
        float hbv = (1.0f - zb) * nb;

        float cacc = 0.0f;
        if (l < HID) cacc = __ldg(wlin + l) * hown + __ldg(wlin + HID + l) * hbv;
        cacc += __shfl_down_sync(m, cacc, 8);
        cacc += __shfl_down_sync(m, cacc, 4);
        cacc += __shfl_down_sync(m, cacc, 2);
        cacc += __shfl_down_sync(m, cacc, 1);
        if (l == 0) out[b] = cacc + __ldg(blin);
    }
}

extern "C" void kernel_launch(void* const* d_in, const int* in_sizes, int n_in,
                              void* d_out, int out_size)
{
    const float* x      = (const float*)d_in[0];
    const float* w_ih_f = (const float*)d_in[1];
    const float* w_hh_f = (const float*)d_in[2];
    const float* b_ih_f = (const float*)d_in[3];
    const float* b_hh_f = (const float*)d_in[4];
    const float* w_ih_b = (const float*)d_in[5];
    /* w_hh_b (d_in[6]) mathematically unused: h0 = 0 for the single bwd step */
    const float* b_ih_b = (const float*)d_in[7];
    const float* b_hh_b = (const float*)d_in[8];
    const float* w_lin  = (const float*)d_in[9];
    const float* b_lin  = (const float*)d_in[10];
    float* out = (float*)d_out;

    k_prep<<<5, 128>>>(w_ih_f);

    cudaFuncSetAttribute(k_fused, cudaFuncAttributeMaxDynamicSharedMemorySize,
                         SMEM_B);
    k_fused<<<BATCH / 2, 192, SMEM_B>>>(x, b_ih_f, w_ih_b, b_ih_b,
                                        w_hh_f, b_hh_f, b_hh_b, w_lin, b_lin,
                                        out);
}